// round 5
// baseline (speedup 1.0000x reference)
#include <cuda_runtime.h>
#include <cuda_bf16.h>
#include <cstdint>

#define N_TOK 4096
#define DIN   512
#define DOUT  512
#define PNUM  8
#define QDIM  4096

// GEMM tiling: 128x128 CTA tile, BK=64, 8 warps (2x4), warp tile 64x32.
// Smem tile: 128 rows x 128B, XOR-swizzled 16B granules (no padding).
#define TILE_B   16384              // 128 * 128
#define BUF_B    (4 * TILE_B)       // Ah, Al, Bh, Bl = 65536
#define GEMM_SMEM (2 * BUF_B)       // 131072 (2-stage)

// ---------------- scratch (static device globals) ----------------
__device__ __align__(128) __nv_bfloat16 g_phi_h[N_TOK * QDIM];
__device__ __align__(128) __nv_bfloat16 g_phi_l[N_TOK * QDIM];
__device__ __align__(128) __nv_bfloat16 g_wphi_h[DOUT * QDIM];
__device__ __align__(128) __nv_bfloat16 g_wphi_l[DOUT * QDIM];
__device__ __align__(128) __nv_bfloat16 g_x_h[N_TOK * DIN];
__device__ __align__(128) __nv_bfloat16 g_x_l[N_TOK * DIN];
__device__ __align__(128) __nv_bfloat16 g_w2_h[PNUM * DOUT * DOUT];
__device__ __align__(128) __nv_bfloat16 g_w2_l[PNUM * DOUT * DOUT];
__device__ __align__(128) __nv_bfloat16 g_zwT_h[PNUM * DIN * DOUT];
__device__ __align__(128) __nv_bfloat16 g_zwT_l[PNUM * DIN * DOUT];
__device__ __align__(128) __nv_bfloat16 g_z0_h[PNUM * N_TOK * DOUT];
__device__ __align__(128) __nv_bfloat16 g_z0_l[PNUM * N_TOK * DOUT];
__device__ __align__(128) float g_xproj[N_TOK * DOUT];

// ---------------- helpers ----------------
__device__ __forceinline__ float sp_f(float v) {
    return fmaxf(v, 0.0f) + log1pf(expf(-fabsf(v)));
}
__device__ __forceinline__ float sig_f(float v) { return 1.0f / (1.0f + expf(-v)); }

__device__ __forceinline__ void split_bf16(float v, __nv_bfloat16& h, __nv_bfloat16& l) {
    h = __float2bfloat16_rn(v);
    l = __float2bfloat16_rn(v - __bfloat162float(h));
}

__device__ __forceinline__ uint32_t smem_u32(const void* p) {
    uint32_t a;
    asm("{ .reg .u64 t; cvta.to.shared.u64 t, %1; cvt.u32.u64 %0, t; }" : "=r"(a) : "l"(p));
    return a;
}

__device__ __forceinline__ void cp16(uint32_t saddr, const void* g) {
    asm volatile("cp.async.cg.shared.global [%0], [%1], 16;" :: "r"(saddr), "l"(g));
}

__device__ __forceinline__ void ldsm4(uint32_t* r, uint32_t addr) {
    asm volatile("ldmatrix.sync.aligned.m8n8.x4.shared.b16 {%0,%1,%2,%3}, [%4];"
                 : "=r"(r[0]), "=r"(r[1]), "=r"(r[2]), "=r"(r[3]) : "r"(addr));
}

__device__ __forceinline__ void mma16816(float* c, const uint32_t* a, const uint32_t* b) {
    asm volatile(
        "mma.sync.aligned.m16n8k16.row.col.f32.bf16.bf16.f32 "
        "{%0,%1,%2,%3}, {%4,%5,%6,%7}, {%8,%9}, {%0,%1,%2,%3};"
        : "+f"(c[0]), "+f"(c[1]), "+f"(c[2]), "+f"(c[3])
        : "r"(a[0]), "r"(a[1]), "r"(a[2]), "r"(a[3]), "r"(b[0]), "r"(b[1]));
}

// ---------------- elementwise kernels ----------------
__global__ void prep_w_kernel(const float* __restrict__ phi_raw,
                              const float* __restrict__ rw2) {
    int idx = blockIdx.x * 256 + threadIdx.x;
    if (idx >= DOUT * QDIM) return;  // 2097152
    float s1 = sp_f(phi_raw[idx]);
    split_bf16(s1 * s1, g_wphi_h[idx], g_wphi_l[idx]);
    float s2 = sp_f(rw2[idx]);
    split_bf16(s2 * s2, g_w2_h[idx], g_w2_l[idx]);
}

// zwT[p][e][c] = zw[p][c][e] + zw[p][c+512][e], coalesced via smem tile
__global__ void prep_zw_kernel(const float* __restrict__ zw) {
    __shared__ float s[32][33];
    const int p = blockIdx.z;
    const int e0 = blockIdx.x * 32;
    const int c0 = blockIdx.y * 32;
    const int tx = threadIdx.x & 31, ty = threadIdx.x >> 5;  // 32 x 8
    const float* zp = zw + (size_t)p * (2 * DIN * DOUT);
#pragma unroll
    for (int r = 0; r < 4; r++) {
        int c = c0 + ty + r * 8;
        s[ty + r * 8][tx] = zp[(size_t)c * DOUT + e0 + tx] +
                            zp[(size_t)(c + DIN) * DOUT + e0 + tx];
    }
    __syncthreads();
#pragma unroll
    for (int r = 0; r < 4; r++) {
        int e = e0 + ty + r * 8;
        size_t dst = (size_t)p * (DIN * DOUT) + (size_t)e * DIN + c0 + tx;
        split_bf16(s[tx][ty + r * 8], g_zwT_h[dst], g_zwT_l[dst]);
    }
}

__global__ void phi_kernel(const float* __restrict__ x) {
    int idx = blockIdx.x * 256 + threadIdx.x;  // N_TOK*DIN
    if (idx >= N_TOK * DIN) return;
    float v = x[idx];
    split_bf16(v, g_x_h[idx], g_x_l[idx]);
    const float step = 2.0f / 7.0f;
    __nv_bfloat16 h8[8], l8[8];
#pragma unroll
    for (int k = 0; k < 8; k++) {
        float f = sp_f(v - 1.0f + step * (float)k);
        split_bf16(f, h8[k], l8[k]);
    }
    *reinterpret_cast<uint4*>(&g_phi_h[(size_t)idx * 8]) = *reinterpret_cast<uint4*>(h8);
    *reinterpret_cast<uint4*>(&g_phi_l[(size_t)idx * 8]) = *reinterpret_cast<uint4*>(l8);
}

__global__ void z0_kernel(const float* __restrict__ gate_raw) {
    int idx4 = blockIdx.x * 256 + threadIdx.x;  // 4194304
    if (idx4 >= (PNUM * N_TOK * DOUT) / 4) return;
    int p = idx4 >> 19;
    float g1 = sig_f(gate_raw[p]);
    int off4 = idx4 & 524287;
    float4 v = *reinterpret_cast<const float4*>(&g_xproj[(size_t)off4 * 4]);
    __nv_bfloat16 h4[4], l4[4];
    split_bf16(sp_f(v.x * g1), h4[0], l4[0]);
    split_bf16(sp_f(v.y * g1), h4[1], l4[1]);
    split_bf16(sp_f(v.z * g1), h4[2], l4[2]);
    split_bf16(sp_f(v.w * g1), h4[3], l4[3]);
    *reinterpret_cast<uint2*>(&g_z0_h[(size_t)idx4 * 4]) = *reinterpret_cast<uint2*>(h4);
    *reinterpret_cast<uint2*>(&g_z0_l[(size_t)idx4 * 4]) = *reinterpret_cast<uint2*>(l4);
}

// ---------------- mma.sync GEMM machinery (BK=64, xor-swizzled smem) ----------------
// smem physical offset(row, g16) = row*128 + ((g16 ^ (row&7)) << 4)

__device__ __forceinline__ void load_chunk(uint32_t dst, const __nv_bfloat16* const* srcs,
                                           int ldk, int k0, int tid) {
    const int g = tid & 7;
    const int rbase = tid >> 3;  // 0..31
#pragma unroll
    for (int t = 0; t < 4; t++) {
        const __nv_bfloat16* s = srcs[t] + k0 + g * 8;
        uint32_t d = dst + t * TILE_B;
#pragma unroll
        for (int j = 0; j < 4; j++) {
            int row = rbase + j * 32;
            cp16(d + row * 128 + (((g ^ (row & 7))) << 4), s + (size_t)row * ldk);
        }
    }
    asm volatile("cp.async.commit_group;" ::: "memory");
}

__device__ __forceinline__ void compute_chunk(uint32_t base, int lane, int wm, int wn,
                                              float (*acc)[4]) {
    const uint32_t xo = lane & 7;
    const uint32_t a_row = wm * 64 + (lane & 15);
    const uint32_t a_g0 = lane >> 4;
    const uint32_t b_row = wn * 32 + (lane & 7) + ((lane >> 4) & 1) * 8;
    const uint32_t b_g0 = (lane >> 3) & 1;
#pragma unroll
    for (int ks = 0; ks < 4; ks++) {
        uint32_t ag = ((a_g0 + ks * 2) ^ xo) << 4;
        uint32_t bg = ((b_g0 + ks * 2) ^ xo) << 4;
        uint32_t ah[4][4], al[4][4], bh[2][4], bl[2][4];
#pragma unroll
        for (int mi = 0; mi < 4; mi++) {
            uint32_t ro = (a_row + mi * 16) * 128 + ag;
            ldsm4(ah[mi], base + ro);
            ldsm4(al[mi], base + TILE_B + ro);
        }
#pragma unroll
        for (int pr = 0; pr < 2; pr++) {
            uint32_t ro = (b_row + pr * 16) * 128 + bg;
            ldsm4(bh[pr], base + 2 * TILE_B + ro);
            ldsm4(bl[pr], base + 3 * TILE_B + ro);
        }
#pragma unroll
        for (int mi = 0; mi < 4; mi++)
#pragma unroll
            for (int ni = 0; ni < 4; ni++) {
                const uint32_t* bhf = &bh[ni >> 1][(ni & 1) * 2];
                const uint32_t* blf = &bl[ni >> 1][(ni & 1) * 2];
                mma16816(acc[mi * 4 + ni], ah[mi], bhf);
                mma16816(acc[mi * 4 + ni], ah[mi], blf);
                mma16816(acc[mi * 4 + ni], al[mi], bhf);
            }
    }
}

// full pipelined GEMM pass: acc += A*B^T over K
__device__ __forceinline__ void run_gemm(const __nv_bfloat16* const* srcs, int ldk, int K,
                                         uint32_t sb, int tid, int lane, int wm, int wn,
                                         float (*acc)[4]) {
    const int nch = K >> 6;
    load_chunk(sb, srcs, ldk, 0, tid);
    for (int i = 0; i < nch; i++) {
        int b = i & 1;
        if (i + 1 < nch) {
            load_chunk(sb + (b ^ 1) * BUF_B, srcs, ldk, (i + 1) << 6, tid);
            asm volatile("cp.async.wait_group 1;" ::: "memory");
        } else {
            asm volatile("cp.async.wait_group 0;" ::: "memory");
        }
        __syncthreads();
        compute_chunk(sb + b * BUF_B, lane, wm, wn, acc);
        __syncthreads();
    }
}

// ---------------- GEMM kernels ----------------
__global__ __launch_bounds__(256) void gemmA_mma(const float* __restrict__ phi_bias) {
    extern __shared__ char smem[];
    uint32_t sb = smem_u32(smem);
    const int tid = threadIdx.x, lane = tid & 31, wid = tid >> 5;
    const int wm = wid & 1, wn = wid >> 1;
    const int m0 = blockIdx.y * 128, n0 = blockIdx.x * 128;

    float acc[16][4];
#pragma unroll
    for (int i = 0; i < 16; i++)
#pragma unroll
        for (int j = 0; j < 4; j++) acc[i][j] = 0.0f;

    const __nv_bfloat16* srcs[4] = {g_phi_h + (size_t)m0 * QDIM, g_phi_l + (size_t)m0 * QDIM,
                                    g_wphi_h + (size_t)n0 * QDIM, g_wphi_l + (size_t)n0 * QDIM};
    run_gemm(srcs, QDIM, QDIM, sb, tid, lane, wm, wn, acc);

    const int g = lane >> 2, t4 = lane & 3;
#pragma unroll
    for (int mi = 0; mi < 4; mi++)
#pragma unroll
        for (int ni = 0; ni < 4; ni++) {
            float* c = acc[mi * 4 + ni];
            int r0 = m0 + wm * 64 + mi * 16 + g;
            int col = n0 + wn * 32 + ni * 8 + t4 * 2;
            float2 b = *reinterpret_cast<const float2*>(&phi_bias[col]);
            *reinterpret_cast<float2*>(&g_xproj[(size_t)r0 * DOUT + col]) =
                make_float2(c[0] + b.x, c[1] + b.y);
            *reinterpret_cast<float2*>(&g_xproj[(size_t)(r0 + 8) * DOUT + col]) =
                make_float2(c[2] + b.x, c[3] + b.y);
        }
}

// fused stage B: acc2 = x @ zwT^T ; acc1 = z0 @ w2^T ; nonlinear combine -> out
__global__ __launch_bounds__(256) void stageB_fused(const float* __restrict__ bias2,
                                                    const float* __restrict__ graw2,
                                                    const float* __restrict__ obias,
                                                    float* __restrict__ out) {
    extern __shared__ char smem[];
    uint32_t sb = smem_u32(smem);
    const int tid = threadIdx.x, lane = tid & 31, wid = tid >> 5;
    const int wm = wid & 1, wn = wid >> 1;
    const int p = blockIdx.z;
    const int m0 = blockIdx.y * 128, n0 = blockIdx.x * 128;

    float acc1[16][4], acc2[16][4];
#pragma unroll
    for (int i = 0; i < 16; i++)
#pragma unroll
        for (int j = 0; j < 4; j++) { acc1[i][j] = 0.0f; acc2[i][j] = 0.0f; }

    {   // residual GEMM: x[m,:] . zwT[p][n,:]
        const size_t bo = (size_t)p * (DIN * DOUT);
        const __nv_bfloat16* srcs[4] = {g_x_h + (size_t)m0 * DIN, g_x_l + (size_t)m0 * DIN,
                                        g_zwT_h + bo + (size_t)n0 * DIN,
                                        g_zwT_l + bo + (size_t)n0 * DIN};
        run_gemm(srcs, DIN, DIN, sb, tid, lane, wm, wn, acc2);
    }
    __syncthreads();
    {   // main GEMM: z0_p[m,:] . w2_p[n,:]
        const size_t ao = (size_t)p * (N_TOK * DOUT);
        const size_t wo = (size_t)p * (DOUT * DOUT);
        const __nv_bfloat16* srcs[4] = {g_z0_h + ao + (size_t)m0 * DOUT,
                                        g_z0_l + ao + (size_t)m0 * DOUT,
                                        g_w2_h + wo + (size_t)n0 * DOUT,
                                        g_w2_l + wo + (size_t)n0 * DOUT};
        run_gemm(srcs, DOUT, DOUT, sb, tid, lane, wm, wn, acc1);
    }

    const float g2 = sig_f(graw2[p]);
    const int g = lane >> 2, t4 = lane & 3;
#pragma unroll
    for (int mi = 0; mi < 4; mi++)
#pragma unroll
        for (int ni = 0; ni < 4; ni++) {
            float* c1 = acc1[mi * 4 + ni];
            float* c2 = acc2[mi * 4 + ni];
            int r0 = m0 + wm * 64 + mi * 16 + g;
            int col = n0 + wn * 32 + ni * 8 + t4 * 2;
            float2 b2 = *reinterpret_cast<const float2*>(&bias2[p * DOUT + col]);
            float2 ob = *reinterpret_cast<const float2*>(&obias[p * DOUT + col]);
            float o0 = sp_f(sp_f((c1[0] + b2.x) * g2) + c2[0]) + ob.x;
            float o1 = sp_f(sp_f((c1[1] + b2.y) * g2) + c2[1]) + ob.y;
            *reinterpret_cast<float2*>(&out[(size_t)r0 * (PNUM * DOUT) + p * DOUT + col]) =
                make_float2(o0, o1);
            float o2 = sp_f(sp_f((c1[2] + b2.x) * g2) + c2[2]) + ob.x;
            float o3 = sp_f(sp_f((c1[3] + b2.y) * g2) + c2[3]) + ob.y;
            *reinterpret_cast<float2*>(&out[(size_t)(r0 + 8) * (PNUM * DOUT) + p * DOUT + col]) =
                make_float2(o2, o3);
        }
}

// ---------------- launch ----------------
extern "C" void kernel_launch(void* const* d_in, const int* in_sizes, int n_in,
                              void* d_out, int out_size) {
    const float* x        = (const float*)d_in[0];
    const float* phi_raw  = (const float*)d_in[1];
    const float* phi_bias = (const float*)d_in[2];
    const float* rw2      = (const float*)d_in[3];
    const float* bias2    = (const float*)d_in[4];
    const float* graw2    = (const float*)d_in[5];
    const float* zw       = (const float*)d_in[6];
    const float* graw     = (const float*)d_in[7];
    const float* obias    = (const float*)d_in[8];
    float* out = (float*)d_out;

    cudaFuncSetAttribute(gemmA_mma,   cudaFuncAttributeMaxDynamicSharedMemorySize, GEMM_SMEM);
    cudaFuncSetAttribute(stageB_fused, cudaFuncAttributeMaxDynamicSharedMemorySize, GEMM_SMEM);

    prep_w_kernel<<<8192, 256>>>(phi_raw, rw2);
    prep_zw_kernel<<<dim3(16, 16, 8), 256>>>(zw);
    phi_kernel<<<8192, 256>>>(x);
    gemmA_mma<<<dim3(4, 32), 256, GEMM_SMEM>>>(phi_bias);
    z0_kernel<<<16384, 256>>>(graw);
    stageB_fused<<<dim3(4, 32, 8), 256, GEMM_SMEM>>>(bias2, graw2, obias, out);
}

// round 6
// speedup vs baseline: 1.2816x; 1.2816x over previous
#include <cuda_runtime.h>
#include <cuda_bf16.h>
#include <cstdint>

#define N_TOK 4096
#define DIN   512
#define DOUT  512
#define PNUM  8
#define QDIM  4096

// GEMM tiling: 128x128 CTA tile, BK=32, 8 warps (2x4), warp tile 64x32.
// Smem tile: 128 rows x 64B, XOR-swizzled 16B granules: off = row*64 + ((g ^ ((row>>1)&3))<<4)
#define TILE_B   8192               // 128 * 64
#define BUF_B    (4 * TILE_B)       // Ah, Al, Bh, Bl = 32768
#define NSTAGE   3
#define GEMM_SMEM (NSTAGE * BUF_B)  // 98304 -> 2 CTAs/SM

// ---------------- scratch (static device globals) ----------------
__device__ __align__(128) __nv_bfloat16 g_phi_h[N_TOK * QDIM];
__device__ __align__(128) __nv_bfloat16 g_phi_l[N_TOK * QDIM];
__device__ __align__(128) __nv_bfloat16 g_wphi_h[DOUT * QDIM];
__device__ __align__(128) __nv_bfloat16 g_wphi_l[DOUT * QDIM];
__device__ __align__(128) __nv_bfloat16 g_x_h[N_TOK * DIN];
__device__ __align__(128) __nv_bfloat16 g_x_l[N_TOK * DIN];
__device__ __align__(128) __nv_bfloat16 g_w2_h[PNUM * DOUT * DOUT];
__device__ __align__(128) __nv_bfloat16 g_w2_l[PNUM * DOUT * DOUT];
__device__ __align__(128) __nv_bfloat16 g_zwT_h[PNUM * DIN * DOUT];
__device__ __align__(128) __nv_bfloat16 g_zwT_l[PNUM * DIN * DOUT];
__device__ __align__(128) __nv_bfloat16 g_z0_h[PNUM * N_TOK * DOUT];
__device__ __align__(128) __nv_bfloat16 g_z0_l[PNUM * N_TOK * DOUT];
__device__ __align__(128) float g_xproj[N_TOK * DOUT];
__device__ __align__(128) float g_acc2[PNUM * N_TOK * DOUT];

// ---------------- helpers ----------------
__device__ __forceinline__ float sp_f(float v) {
    return fmaxf(v, 0.0f) + log1pf(expf(-fabsf(v)));
}
__device__ __forceinline__ float sig_f(float v) { return 1.0f / (1.0f + expf(-v)); }

__device__ __forceinline__ void split_bf16(float v, __nv_bfloat16& h, __nv_bfloat16& l) {
    h = __float2bfloat16_rn(v);
    l = __float2bfloat16_rn(v - __bfloat162float(h));
}

__device__ __forceinline__ uint32_t smem_u32(const void* p) {
    uint32_t a;
    asm("{ .reg .u64 t; cvta.to.shared.u64 t, %1; cvt.u32.u64 %0, t; }" : "=r"(a) : "l"(p));
    return a;
}

__device__ __forceinline__ void cp16(uint32_t saddr, const void* g) {
    asm volatile("cp.async.cg.shared.global [%0], [%1], 16;" :: "r"(saddr), "l"(g));
}

__device__ __forceinline__ void ldsm4(uint32_t* r, uint32_t addr) {
    asm volatile("ldmatrix.sync.aligned.m8n8.x4.shared.b16 {%0,%1,%2,%3}, [%4];"
                 : "=r"(r[0]), "=r"(r[1]), "=r"(r[2]), "=r"(r[3]) : "r"(addr));
}

__device__ __forceinline__ void mma16816(float* c, const uint32_t* a, const uint32_t* b) {
    asm volatile(
        "mma.sync.aligned.m16n8k16.row.col.f32.bf16.bf16.f32 "
        "{%0,%1,%2,%3}, {%4,%5,%6,%7}, {%8,%9}, {%0,%1,%2,%3};"
        : "+f"(c[0]), "+f"(c[1]), "+f"(c[2]), "+f"(c[3])
        : "r"(a[0]), "r"(a[1]), "r"(a[2]), "r"(a[3]), "r"(b[0]), "r"(b[1]));
}

// ---------------- elementwise kernels ----------------
__global__ void prep_w_kernel(const float* __restrict__ phi_raw,
                              const float* __restrict__ rw2) {
    int idx = blockIdx.x * 256 + threadIdx.x;
    if (idx >= DOUT * QDIM) return;  // 2097152
    float s1 = sp_f(phi_raw[idx]);
    split_bf16(s1 * s1, g_wphi_h[idx], g_wphi_l[idx]);
    float s2 = sp_f(rw2[idx]);
    split_bf16(s2 * s2, g_w2_h[idx], g_w2_l[idx]);
}

// zwT[p][e][c] = zw[p][c][e] + zw[p][c+512][e], coalesced via smem tile
__global__ void prep_zw_kernel(const float* __restrict__ zw) {
    __shared__ float s[32][33];
    const int p = blockIdx.z;
    const int e0 = blockIdx.x * 32;
    const int c0 = blockIdx.y * 32;
    const int tx = threadIdx.x & 31, ty = threadIdx.x >> 5;  // 32 x 8
    const float* zp = zw + (size_t)p * (2 * DIN * DOUT);
#pragma unroll
    for (int r = 0; r < 4; r++) {
        int c = c0 + ty + r * 8;
        s[ty + r * 8][tx] = zp[(size_t)c * DOUT + e0 + tx] +
                            zp[(size_t)(c + DIN) * DOUT + e0 + tx];
    }
    __syncthreads();
#pragma unroll
    for (int r = 0; r < 4; r++) {
        int e = e0 + ty + r * 8;
        size_t dst = (size_t)p * (DIN * DOUT) + (size_t)e * DIN + c0 + tx;
        split_bf16(s[tx][ty + r * 8], g_zwT_h[dst], g_zwT_l[dst]);
    }
}

__global__ void phi_kernel(const float* __restrict__ x) {
    int idx = blockIdx.x * 256 + threadIdx.x;  // N_TOK*DIN
    if (idx >= N_TOK * DIN) return;
    float v = x[idx];
    split_bf16(v, g_x_h[idx], g_x_l[idx]);
    const float step = 2.0f / 7.0f;
    __nv_bfloat16 h8[8], l8[8];
#pragma unroll
    for (int k = 0; k < 8; k++) {
        float f = sp_f(v - 1.0f + step * (float)k);
        split_bf16(f, h8[k], l8[k]);
    }
    *reinterpret_cast<uint4*>(&g_phi_h[(size_t)idx * 8]) = *reinterpret_cast<uint4*>(h8);
    *reinterpret_cast<uint4*>(&g_phi_l[(size_t)idx * 8]) = *reinterpret_cast<uint4*>(l8);
}

__global__ void z0_kernel(const float* __restrict__ gate_raw) {
    int idx4 = blockIdx.x * 256 + threadIdx.x;  // 4194304
    if (idx4 >= (PNUM * N_TOK * DOUT) / 4) return;
    int p = idx4 >> 19;
    float g1 = sig_f(gate_raw[p]);
    int off4 = idx4 & 524287;
    float4 v = *reinterpret_cast<const float4*>(&g_xproj[(size_t)off4 * 4]);
    __nv_bfloat16 h4[4], l4[4];
    split_bf16(sp_f(v.x * g1), h4[0], l4[0]);
    split_bf16(sp_f(v.y * g1), h4[1], l4[1]);
    split_bf16(sp_f(v.z * g1), h4[2], l4[2]);
    split_bf16(sp_f(v.w * g1), h4[3], l4[3]);
    *reinterpret_cast<uint2*>(&g_z0_h[(size_t)idx4 * 4]) = *reinterpret_cast<uint2*>(h4);
    *reinterpret_cast<uint2*>(&g_z0_l[(size_t)idx4 * 4]) = *reinterpret_cast<uint2*>(l4);
}

// ---------------- mma.sync GEMM machinery (BK=32, xor-swizzled smem) ----------------
__device__ __forceinline__ void load_chunk(uint32_t dst, const __nv_bfloat16* const* srcs,
                                           int ldk, int k0, int tid) {
    const int g = tid & 3;
    const int rbase = tid >> 2;  // 0..63
#pragma unroll
    for (int t = 0; t < 4; t++) {
        const __nv_bfloat16* s = srcs[t] + k0 + g * 8;
        uint32_t d = dst + t * TILE_B;
#pragma unroll
        for (int j = 0; j < 2; j++) {
            int row = rbase + j * 64;
            cp16(d + row * 64 + ((g ^ ((row >> 1) & 3)) << 4), s + (size_t)row * ldk);
        }
    }
    asm volatile("cp.async.commit_group;" ::: "memory");
}

__device__ __forceinline__ void compute_chunk(uint32_t base, int lane, int wm, int wn,
                                              float (*acc)[4]) {
    const uint32_t a_row = wm * 64 + (lane & 15);
    const uint32_t a_g0 = lane >> 4;                          // 0/1 (16B half of k16)
    const uint32_t xa = ((lane & 15) >> 1) & 3;
    const uint32_t b_row = wn * 32 + (lane & 7) + ((lane >> 4) & 1) * 8;
    const uint32_t b_g0 = (lane >> 3) & 1;
    const uint32_t xb = ((lane & 7) >> 1) & 3;
#pragma unroll
    for (int ks = 0; ks < 2; ks++) {
        uint32_t ag = ((a_g0 + ks * 2) ^ xa) << 4;
        uint32_t bg = ((b_g0 + ks * 2) ^ xb) << 4;
        uint32_t ah[4][4], al[4][4], bh[2][4], bl[2][4];
#pragma unroll
        for (int mi = 0; mi < 4; mi++) {
            uint32_t ro = (a_row + mi * 16) * 64 + ag;
            ldsm4(ah[mi], base + ro);
            ldsm4(al[mi], base + TILE_B + ro);
        }
#pragma unroll
        for (int pr = 0; pr < 2; pr++) {
            uint32_t ro = (b_row + pr * 16) * 64 + bg;
            ldsm4(bh[pr], base + 2 * TILE_B + ro);
            ldsm4(bl[pr], base + 3 * TILE_B + ro);
        }
#pragma unroll
        for (int mi = 0; mi < 4; mi++)
#pragma unroll
            for (int ni = 0; ni < 4; ni++) {
                const uint32_t* bhf = &bh[ni >> 1][(ni & 1) * 2];
                const uint32_t* blf = &bl[ni >> 1][(ni & 1) * 2];
                mma16816(acc[mi * 4 + ni], ah[mi], bhf);
                mma16816(acc[mi * 4 + ni], ah[mi], blf);
                mma16816(acc[mi * 4 + ni], al[mi], bhf);
            }
    }
}

// 3-stage pipelined GEMM pass: acc += A*B^T over K. One barrier per chunk.
__device__ __forceinline__ void run_gemm(const __nv_bfloat16* const* srcs, int ldk, int K,
                                         uint32_t sb, int tid, int lane, int wm, int wn,
                                         float (*acc)[4]) {
    const int nch = K >> 5;
    load_chunk(sb, srcs, ldk, 0, tid);
    load_chunk(sb + BUF_B, srcs, ldk, 32, tid);
    int buf = 0;
    for (int i = 0; i < nch; i++) {
        if (i + 1 < nch) {
            asm volatile("cp.async.wait_group 1;" ::: "memory");
        } else {
            asm volatile("cp.async.wait_group 0;" ::: "memory");
        }
        __syncthreads();
        if (i + 2 < nch) {
            int nb = buf + 2; if (nb >= NSTAGE) nb -= NSTAGE;
            load_chunk(sb + nb * BUF_B, srcs, ldk, (i + 2) << 5, tid);
        }
        compute_chunk(sb + buf * BUF_B, lane, wm, wn, acc);
        if (++buf == NSTAGE) buf = 0;
    }
}

// ---------------- GEMM kernels ----------------
__global__ __launch_bounds__(256, 2) void gemmA_mma(const float* __restrict__ phi_bias) {
    extern __shared__ char smem[];
    uint32_t sb = smem_u32(smem);
    const int tid = threadIdx.x, lane = tid & 31, wid = tid >> 5;
    const int wm = wid & 1, wn = wid >> 1;
    const int m0 = blockIdx.y * 128, n0 = blockIdx.x * 128;

    float acc[16][4];
#pragma unroll
    for (int i = 0; i < 16; i++)
#pragma unroll
        for (int j = 0; j < 4; j++) acc[i][j] = 0.0f;

    const __nv_bfloat16* srcs[4] = {g_phi_h + (size_t)m0 * QDIM, g_phi_l + (size_t)m0 * QDIM,
                                    g_wphi_h + (size_t)n0 * QDIM, g_wphi_l + (size_t)n0 * QDIM};
    run_gemm(srcs, QDIM, QDIM, sb, tid, lane, wm, wn, acc);

    const int g = lane >> 2, t4 = lane & 3;
#pragma unroll
    for (int mi = 0; mi < 4; mi++)
#pragma unroll
        for (int ni = 0; ni < 4; ni++) {
            float* c = acc[mi * 4 + ni];
            int r0 = m0 + wm * 64 + mi * 16 + g;
            int col = n0 + wn * 32 + ni * 8 + t4 * 2;
            float2 b = *reinterpret_cast<const float2*>(&phi_bias[col]);
            *reinterpret_cast<float2*>(&g_xproj[(size_t)r0 * DOUT + col]) =
                make_float2(c[0] + b.x, c[1] + b.y);
            *reinterpret_cast<float2*>(&g_xproj[(size_t)(r0 + 8) * DOUT + col]) =
                make_float2(c[2] + b.x, c[3] + b.y);
        }
}

// residual GEMM: acc2 = x @ zwT^T  (fp32 round-trip through global)
__global__ __launch_bounds__(256, 2) void stageB2_mma() {
    extern __shared__ char smem[];
    uint32_t sb = smem_u32(smem);
    const int tid = threadIdx.x, lane = tid & 31, wid = tid >> 5;
    const int wm = wid & 1, wn = wid >> 1;
    const int p = blockIdx.z;
    const int m0 = blockIdx.y * 128, n0 = blockIdx.x * 128;

    float acc[16][4];
#pragma unroll
    for (int i = 0; i < 16; i++)
#pragma unroll
        for (int j = 0; j < 4; j++) acc[i][j] = 0.0f;

    const size_t bo = (size_t)p * (DIN * DOUT);
    const __nv_bfloat16* srcs[4] = {g_x_h + (size_t)m0 * DIN, g_x_l + (size_t)m0 * DIN,
                                    g_zwT_h + bo + (size_t)n0 * DIN,
                                    g_zwT_l + bo + (size_t)n0 * DIN};
    run_gemm(srcs, DIN, DIN, sb, tid, lane, wm, wn, acc);

    float* C = g_acc2 + (size_t)p * (N_TOK * DOUT);
    const int g = lane >> 2, t4 = lane & 3;
#pragma unroll
    for (int mi = 0; mi < 4; mi++)
#pragma unroll
        for (int ni = 0; ni < 4; ni++) {
            float* c = acc[mi * 4 + ni];
            int r0 = m0 + wm * 64 + mi * 16 + g;
            int col = n0 + wn * 32 + ni * 8 + t4 * 2;
            *reinterpret_cast<float2*>(&C[(size_t)r0 * DOUT + col]) = make_float2(c[0], c[1]);
            *reinterpret_cast<float2*>(&C[(size_t)(r0 + 8) * DOUT + col]) = make_float2(c[2], c[3]);
        }
}

// main GEMM: z0 @ w2^T with fused nonlinear epilogue (reads acc2) -> out
__global__ __launch_bounds__(256, 2) void stageB1_mma(const float* __restrict__ bias2,
                                                      const float* __restrict__ graw2,
                                                      const float* __restrict__ obias,
                                                      float* __restrict__ out) {
    extern __shared__ char smem[];
    uint32_t sb = smem_u32(smem);
    const int tid = threadIdx.x, lane = tid & 31, wid = tid >> 5;
    const int wm = wid & 1, wn = wid >> 1;
    const int p = blockIdx.z;
    const int m0 = blockIdx.y * 128, n0 = blockIdx.x * 128;

    float acc[16][4];
#pragma unroll
    for (int i = 0; i < 16; i++)
#pragma unroll
        for (int j = 0; j < 4; j++) acc[i][j] = 0.0f;

    const size_t ao = (size_t)p * (N_TOK * DOUT);
    const size_t wo = (size_t)p * (DOUT * DOUT);
    const __nv_bfloat16* srcs[4] = {g_z0_h + ao + (size_t)m0 * DOUT,
                                    g_z0_l + ao + (size_t)m0 * DOUT,
                                    g_w2_h + wo + (size_t)n0 * DOUT,
                                    g_w2_l + wo + (size_t)n0 * DOUT};
    run_gemm(srcs, DOUT, DOUT, sb, tid, lane, wm, wn, acc);

    const float g2 = sig_f(graw2[p]);
    const float* acc2 = g_acc2 + ao;
    const int g = lane >> 2, t4 = lane & 3;
#pragma unroll
    for (int mi = 0; mi < 4; mi++)
#pragma unroll
        for (int ni = 0; ni < 4; ni++) {
            float* c1 = acc[mi * 4 + ni];
            int r0 = m0 + wm * 64 + mi * 16 + g;
            int col = n0 + wn * 32 + ni * 8 + t4 * 2;
            float2 b2 = *reinterpret_cast<const float2*>(&bias2[p * DOUT + col]);
            float2 ob = *reinterpret_cast<const float2*>(&obias[p * DOUT + col]);
            float2 a2a = *reinterpret_cast<const float2*>(&acc2[(size_t)r0 * DOUT + col]);
            float2 a2b = *reinterpret_cast<const float2*>(&acc2[(size_t)(r0 + 8) * DOUT + col]);
            float o0 = sp_f(sp_f((c1[0] + b2.x) * g2) + a2a.x) + ob.x;
            float o1 = sp_f(sp_f((c1[1] + b2.y) * g2) + a2a.y) + ob.y;
            *reinterpret_cast<float2*>(&out[(size_t)r0 * (PNUM * DOUT) + p * DOUT + col]) =
                make_float2(o0, o1);
            float o2 = sp_f(sp_f((c1[2] + b2.x) * g2) + a2b.x) + ob.x;
            float o3 = sp_f(sp_f((c1[3] + b2.y) * g2) + a2b.y) + ob.y;
            *reinterpret_cast<float2*>(&out[(size_t)(r0 + 8) * (PNUM * DOUT) + p * DOUT + col]) =
                make_float2(o2, o3);
        }
}

// ---------------- launch ----------------
extern "C" void kernel_launch(void* const* d_in, const int* in_sizes, int n_in,
                              void* d_out, int out_size) {
    const float* x        = (const float*)d_in[0];
    const float* phi_raw  = (const float*)d_in[1];
    const float* phi_bias = (const float*)d_in[2];
    const float* rw2      = (const float*)d_in[3];
    const float* bias2    = (const float*)d_in[4];
    const float* graw2    = (const float*)d_in[5];
    const float* zw       = (const float*)d_in[6];
    const float* graw     = (const float*)d_in[7];
    const float* obias    = (const float*)d_in[8];
    float* out = (float*)d_out;

    cudaFuncSetAttribute(gemmA_mma,   cudaFuncAttributeMaxDynamicSharedMemorySize, GEMM_SMEM);
    cudaFuncSetAttribute(stageB2_mma, cudaFuncAttributeMaxDynamicSharedMemorySize, GEMM_SMEM);
    cudaFuncSetAttribute(stageB1_mma, cudaFuncAttributeMaxDynamicSharedMemorySize, GEMM_SMEM);

    prep_w_kernel<<<8192, 256>>>(phi_raw, rw2);
    prep_zw_kernel<<<dim3(16, 16, 8), 256>>>(zw);
    phi_kernel<<<8192, 256>>>(x);
    gemmA_mma<<<dim3(4, 32), 256, GEMM_SMEM>>>(phi_bias);
    z0_kernel<<<16384, 256>>>(graw);
    stageB2_mma<<<dim3(4, 32, 8), 256, GEMM_SMEM>>>();
    stageB1_mma<<<dim3(4, 32, 8), 256, GEMM_SMEM>>>(bias2, graw2, obias, out);
}

// round 7
// speedup vs baseline: 1.4193x; 1.1074x over previous
#include <cuda_runtime.h>
#include <cuda_bf16.h>
#include <cstdint>

#define N_TOK 4096
#define DIN   512
#define DOUT  512
#define PNUM  8
#define QDIM  4096

// Tiling: 128x128 CTA tile, BK=32, 8 warps (2x4), warp tile 64x32.
// Smem tile: 128 rows x 64B, XOR-swizzled: off = row*64 + ((g ^ ((row>>1)&3))<<4)
#define TILE_B    8192                 // one operand tile
#define BUF_S     (2 * TILE_B)         // single-MMA: Ah, Bh           = 16384
#define BUF_T     (4 * TILE_B)         // triple-MMA: Ah, Al, Bh, Bl   = 32768
#define NSTAGE_S  4
#define NSTAGE_T  3
#define SMEM_S    (NSTAGE_S * BUF_S)   // 65536
#define SMEM_T    (NSTAGE_T * BUF_T)   // 98304

// ---------------- scratch (static device globals) ----------------
__device__ __align__(128) __nv_bfloat16 g_phi_h[N_TOK * QDIM];
__device__ __align__(128) __nv_bfloat16 g_wphi_h[DOUT * QDIM];
__device__ __align__(128) __nv_bfloat16 g_x_h[N_TOK * DIN];
__device__ __align__(128) __nv_bfloat16 g_x_l[N_TOK * DIN];
__device__ __align__(128) __nv_bfloat16 g_w2_h[PNUM * DOUT * DOUT];
__device__ __align__(128) __nv_bfloat16 g_zwT_h[PNUM * DIN * DOUT];
__device__ __align__(128) __nv_bfloat16 g_zwT_l[PNUM * DIN * DOUT];
__device__ __align__(128) __nv_bfloat16 g_z0_h[PNUM * N_TOK * DOUT];
__device__ __align__(128) float g_acc2[PNUM * N_TOK * DOUT];

// ---------------- helpers ----------------
__device__ __forceinline__ float sp_f(float v) {
    return fmaxf(v, 0.0f) + log1pf(expf(-fabsf(v)));
}
__device__ __forceinline__ float sig_f(float v) { return 1.0f / (1.0f + expf(-v)); }

__device__ __forceinline__ void split_bf16(float v, __nv_bfloat16& h, __nv_bfloat16& l) {
    h = __float2bfloat16_rn(v);
    l = __float2bfloat16_rn(v - __bfloat162float(h));
}

__device__ __forceinline__ uint32_t smem_u32(const void* p) {
    uint32_t a;
    asm("{ .reg .u64 t; cvta.to.shared.u64 t, %1; cvt.u32.u64 %0, t; }" : "=r"(a) : "l"(p));
    return a;
}

__device__ __forceinline__ void cp16(uint32_t saddr, const void* g) {
    asm volatile("cp.async.cg.shared.global [%0], [%1], 16;" :: "r"(saddr), "l"(g));
}

__device__ __forceinline__ void ldsm4(uint32_t* r, uint32_t addr) {
    asm volatile("ldmatrix.sync.aligned.m8n8.x4.shared.b16 {%0,%1,%2,%3}, [%4];"
                 : "=r"(r[0]), "=r"(r[1]), "=r"(r[2]), "=r"(r[3]) : "r"(addr));
}

__device__ __forceinline__ void mma16816(float* c, const uint32_t* a, const uint32_t* b) {
    asm volatile(
        "mma.sync.aligned.m16n8k16.row.col.f32.bf16.bf16.f32 "
        "{%0,%1,%2,%3}, {%4,%5,%6,%7}, {%8,%9}, {%0,%1,%2,%3};"
        : "+f"(c[0]), "+f"(c[1]), "+f"(c[2]), "+f"(c[3])
        : "r"(a[0]), "r"(a[1]), "r"(a[2]), "r"(a[3]), "r"(b[0]), "r"(b[1]));
}

// ---------------- elementwise kernels ----------------
__global__ void prep_w_kernel(const float* __restrict__ phi_raw,
                              const float* __restrict__ rw2) {
    int idx = blockIdx.x * 256 + threadIdx.x;
    if (idx >= DOUT * QDIM) return;  // 2097152
    float s1 = sp_f(phi_raw[idx]);
    g_wphi_h[idx] = __float2bfloat16_rn(s1 * s1);
    float s2 = sp_f(rw2[idx]);
    g_w2_h[idx] = __float2bfloat16_rn(s2 * s2);
}

// zwT[p][e][c] = zw[p][c][e] + zw[p][c+512][e], coalesced via smem tile (hi/lo split)
__global__ void prep_zw_kernel(const float* __restrict__ zw) {
    __shared__ float s[32][33];
    const int p = blockIdx.z;
    const int e0 = blockIdx.x * 32;
    const int c0 = blockIdx.y * 32;
    const int tx = threadIdx.x & 31, ty = threadIdx.x >> 5;  // 32 x 8
    const float* zp = zw + (size_t)p * (2 * DIN * DOUT);
#pragma unroll
    for (int r = 0; r < 4; r++) {
        int c = c0 + ty + r * 8;
        s[ty + r * 8][tx] = zp[(size_t)c * DOUT + e0 + tx] +
                            zp[(size_t)(c + DIN) * DOUT + e0 + tx];
    }
    __syncthreads();
#pragma unroll
    for (int r = 0; r < 4; r++) {
        int e = e0 + ty + r * 8;
        size_t dst = (size_t)p * (DIN * DOUT) + (size_t)e * DIN + c0 + tx;
        split_bf16(s[tx][ty + r * 8], g_zwT_h[dst], g_zwT_l[dst]);
    }
}

__global__ void phi_kernel(const float* __restrict__ x) {
    int idx = blockIdx.x * 256 + threadIdx.x;  // N_TOK*DIN
    if (idx >= N_TOK * DIN) return;
    float v = x[idx];
    split_bf16(v, g_x_h[idx], g_x_l[idx]);
    const float step = 2.0f / 7.0f;
    __nv_bfloat16 h8[8];
#pragma unroll
    for (int k = 0; k < 8; k++)
        h8[k] = __float2bfloat16_rn(sp_f(v - 1.0f + step * (float)k));
    *reinterpret_cast<uint4*>(&g_phi_h[(size_t)idx * 8]) = *reinterpret_cast<uint4*>(h8);
}

// ---------------- shared GEMM machinery ----------------
// swizzled store offset for loader
__device__ __forceinline__ void load_tiles(uint32_t dst, const __nv_bfloat16* const* srcs,
                                           int ntiles, int ldk, int k0, int tid) {
    const int g = tid & 3;
    const int rbase = tid >> 2;  // 0..63
    for (int t = 0; t < ntiles; t++) {
        const __nv_bfloat16* s = srcs[t] + k0 + g * 8;
        uint32_t d = dst + t * TILE_B;
#pragma unroll
        for (int j = 0; j < 2; j++) {
            int row = rbase + j * 64;
            cp16(d + row * 64 + ((g ^ ((row >> 1) & 3)) << 4), s + (size_t)row * ldk);
        }
    }
    asm volatile("cp.async.commit_group;" ::: "memory");
}

// fragment addressing shared by compute paths
struct FragAddr {
    uint32_t a_row, a_g0, xa, b_row, b_g0, xb;
    __device__ FragAddr(int lane, int wm, int wn) {
        a_row = wm * 64 + (lane & 15);
        a_g0 = lane >> 4;
        xa = ((lane & 15) >> 1) & 3;
        b_row = wn * 32 + (lane & 7) + ((lane >> 4) & 1) * 8;
        b_g0 = (lane >> 3) & 1;
        xb = ((lane & 7) >> 1) & 3;
    }
};

// single-MMA chunk: tiles {Ah, Bh}
__device__ __forceinline__ void compute_chunk_s(uint32_t base, const FragAddr& f,
                                                float (*acc)[4]) {
#pragma unroll
    for (int ks = 0; ks < 2; ks++) {
        uint32_t ag = ((f.a_g0 + ks * 2) ^ f.xa) << 4;
        uint32_t bg = ((f.b_g0 + ks * 2) ^ f.xb) << 4;
        uint32_t ah[4][4], bh[2][4];
#pragma unroll
        for (int mi = 0; mi < 4; mi++)
            ldsm4(ah[mi], base + (f.a_row + mi * 16) * 64 + ag);
#pragma unroll
        for (int pr = 0; pr < 2; pr++)
            ldsm4(bh[pr], base + TILE_B + (f.b_row + pr * 16) * 64 + bg);
#pragma unroll
        for (int mi = 0; mi < 4; mi++)
#pragma unroll
            for (int ni = 0; ni < 4; ni++)
                mma16816(acc[mi * 4 + ni], ah[mi], &bh[ni >> 1][(ni & 1) * 2]);
    }
}

// triple-MMA chunk: tiles {Ah, Al, Bh, Bl}
__device__ __forceinline__ void compute_chunk_t(uint32_t base, const FragAddr& f,
                                                float (*acc)[4]) {
#pragma unroll
    for (int ks = 0; ks < 2; ks++) {
        uint32_t ag = ((f.a_g0 + ks * 2) ^ f.xa) << 4;
        uint32_t bg = ((f.b_g0 + ks * 2) ^ f.xb) << 4;
        uint32_t ah[4][4], al[4][4], bh[2][4], bl[2][4];
#pragma unroll
        for (int mi = 0; mi < 4; mi++) {
            uint32_t ro = (f.a_row + mi * 16) * 64 + ag;
            ldsm4(ah[mi], base + ro);
            ldsm4(al[mi], base + TILE_B + ro);
        }
#pragma unroll
        for (int pr = 0; pr < 2; pr++) {
            uint32_t ro = (f.b_row + pr * 16) * 64 + bg;
            ldsm4(bh[pr], base + 2 * TILE_B + ro);
            ldsm4(bl[pr], base + 3 * TILE_B + ro);
        }
#pragma unroll
        for (int mi = 0; mi < 4; mi++)
#pragma unroll
            for (int ni = 0; ni < 4; ni++) {
                const uint32_t* bhf = &bh[ni >> 1][(ni & 1) * 2];
                const uint32_t* blf = &bl[ni >> 1][(ni & 1) * 2];
                mma16816(acc[mi * 4 + ni], ah[mi], bhf);
                mma16816(acc[mi * 4 + ni], ah[mi], blf);
                mma16816(acc[mi * 4 + ni], al[mi], bhf);
            }
    }
}

// 4-stage pipelined single-MMA pass
__device__ __forceinline__ void run_gemm_s(const __nv_bfloat16* const* srcs, int ldk, int K,
                                           uint32_t sb, int tid, const FragAddr& f,
                                           float (*acc)[4]) {
    const int nch = K >> 5;
    load_tiles(sb, srcs, 2, ldk, 0, tid);
    load_tiles(sb + BUF_S, srcs, 2, ldk, 32, tid);
    load_tiles(sb + 2 * BUF_S, srcs, 2, ldk, 64, tid);
    int buf = 0;
    for (int i = 0; i < nch; i++) {
        if (i + 2 < nch) {
            asm volatile("cp.async.wait_group 2;" ::: "memory");
        } else if (i + 1 < nch) {
            asm volatile("cp.async.wait_group 1;" ::: "memory");
        } else {
            asm volatile("cp.async.wait_group 0;" ::: "memory");
        }
        __syncthreads();
        if (i + 3 < nch) {
            int nb = buf + 3; if (nb >= NSTAGE_S) nb -= NSTAGE_S;
            load_tiles(sb + nb * BUF_S, srcs, 2, ldk, (i + 3) << 5, tid);
        }
        compute_chunk_s(sb + buf * BUF_S, f, acc);
        if (++buf == NSTAGE_S) buf = 0;
    }
}

// 3-stage pipelined triple-MMA pass
__device__ __forceinline__ void run_gemm_t(const __nv_bfloat16* const* srcs, int ldk, int K,
                                           uint32_t sb, int tid, const FragAddr& f,
                                           float (*acc)[4]) {
    const int nch = K >> 5;
    load_tiles(sb, srcs, 4, ldk, 0, tid);
    load_tiles(sb + BUF_T, srcs, 4, ldk, 32, tid);
    int buf = 0;
    for (int i = 0; i < nch; i++) {
        if (i + 1 < nch) {
            asm volatile("cp.async.wait_group 1;" ::: "memory");
        } else {
            asm volatile("cp.async.wait_group 0;" ::: "memory");
        }
        __syncthreads();
        if (i + 2 < nch) {
            int nb = buf + 2; if (nb >= NSTAGE_T) nb -= NSTAGE_T;
            load_tiles(sb + nb * BUF_T, srcs, 4, ldk, (i + 2) << 5, tid);
        }
        compute_chunk_t(sb + buf * BUF_T, f, acc);
        if (++buf == NSTAGE_T) buf = 0;
    }
}

// ---------------- GEMM kernels ----------------
// GEMM A (pure bf16) + fused z0 epilogue: writes z0_h[p][n][d] for all 8 experts.
__global__ __launch_bounds__(256, 2) void gemmA_z0(const float* __restrict__ phi_bias,
                                                   const float* __restrict__ graw) {
    extern __shared__ char smem[];
    uint32_t sb = smem_u32(smem);
    const int tid = threadIdx.x, lane = tid & 31, wid = tid >> 5;
    const FragAddr f(lane, wid & 1, wid >> 1);
    const int m0 = blockIdx.y * 128, n0 = blockIdx.x * 128;

    float acc[16][4];
#pragma unroll
    for (int i = 0; i < 16; i++)
#pragma unroll
        for (int j = 0; j < 4; j++) acc[i][j] = 0.0f;

    const __nv_bfloat16* srcs[2] = {g_phi_h + (size_t)m0 * QDIM,
                                    g_wphi_h + (size_t)n0 * QDIM};
    run_gemm_s(srcs, QDIM, QDIM, sb, tid, f, acc);

    float g1[PNUM];
#pragma unroll
    for (int p = 0; p < PNUM; p++) g1[p] = sig_f(graw[p]);

    const int wm = wid & 1, wn = wid >> 1;
    const int g = lane >> 2, t4 = lane & 3;
#pragma unroll
    for (int mi = 0; mi < 4; mi++)
#pragma unroll
        for (int ni = 0; ni < 4; ni++) {
            float* c = acc[mi * 4 + ni];
            int r0 = m0 + wm * 64 + mi * 16 + g;
            int col = n0 + wn * 32 + ni * 8 + t4 * 2;
            float2 b = *reinterpret_cast<const float2*>(&phi_bias[col]);
            float xp[4] = {c[0] + b.x, c[1] + b.y, c[2] + b.x, c[3] + b.y};
#pragma unroll
            for (int p = 0; p < PNUM; p++) {
                __nv_bfloat16 z[4];
#pragma unroll
                for (int q = 0; q < 4; q++)
                    z[q] = __float2bfloat16_rn(sp_f(xp[q] * g1[p]));
                size_t base = (size_t)p * (N_TOK * DOUT);
                *reinterpret_cast<uint32_t*>(&g_z0_h[base + (size_t)r0 * DOUT + col]) =
                    *reinterpret_cast<uint32_t*>(&z[0]);
                *reinterpret_cast<uint32_t*>(&g_z0_h[base + (size_t)(r0 + 8) * DOUT + col]) =
                    *reinterpret_cast<uint32_t*>(&z[2]);
            }
        }
}

// residual GEMM (triple-MMA): acc2 = x @ zwT^T
__global__ __launch_bounds__(256, 2) void stageB2_mma() {
    extern __shared__ char smem[];
    uint32_t sb = smem_u32(smem);
    const int tid = threadIdx.x, lane = tid & 31, wid = tid >> 5;
    const FragAddr f(lane, wid & 1, wid >> 1);
    const int p = blockIdx.z;
    const int m0 = blockIdx.y * 128, n0 = blockIdx.x * 128;

    float acc[16][4];
#pragma unroll
    for (int i = 0; i < 16; i++)
#pragma unroll
        for (int j = 0; j < 4; j++) acc[i][j] = 0.0f;

    const size_t bo = (size_t)p * (DIN * DOUT);
    const __nv_bfloat16* srcs[4] = {g_x_h + (size_t)m0 * DIN, g_x_l + (size_t)m0 * DIN,
                                    g_zwT_h + bo + (size_t)n0 * DIN,
                                    g_zwT_l + bo + (size_t)n0 * DIN};
    run_gemm_t(srcs, DIN, DIN, sb, tid, f, acc);

    float* C = g_acc2 + (size_t)p * (N_TOK * DOUT);
    const int wm = wid & 1, wn = wid >> 1;
    const int g = lane >> 2, t4 = lane & 3;
#pragma unroll
    for (int mi = 0; mi < 4; mi++)
#pragma unroll
        for (int ni = 0; ni < 4; ni++) {
            float* c = acc[mi * 4 + ni];
            int r0 = m0 + wm * 64 + mi * 16 + g;
            int col = n0 + wn * 32 + ni * 8 + t4 * 2;
            *reinterpret_cast<float2*>(&C[(size_t)r0 * DOUT + col]) = make_float2(c[0], c[1]);
            *reinterpret_cast<float2*>(&C[(size_t)(r0 + 8) * DOUT + col]) = make_float2(c[2], c[3]);
        }
}

// main GEMM (pure bf16): z0 @ w2^T + fused nonlinear epilogue -> out
__global__ __launch_bounds__(256, 2) void stageB1_mma(const float* __restrict__ bias2,
                                                      const float* __restrict__ graw2,
                                                      const float* __restrict__ obias,
                                                      float* __restrict__ out) {
    extern __shared__ char smem[];
    uint32_t sb = smem_u32(smem);
    const int tid = threadIdx.x, lane = tid & 31, wid = tid >> 5;
    const FragAddr f(lane, wid & 1, wid >> 1);
    const int p = blockIdx.z;
    const int m0 = blockIdx.y * 128, n0 = blockIdx.x * 128;

    float acc[16][4];
#pragma unroll
    for (int i = 0; i < 16; i++)
#pragma unroll
        for (int j = 0; j < 4; j++) acc[i][j] = 0.0f;

    const size_t ao = (size_t)p * (N_TOK * DOUT);
    const size_t wo = (size_t)p * (DOUT * DOUT);
    const __nv_bfloat16* srcs[2] = {g_z0_h + ao + (size_t)m0 * DOUT,
                                    g_w2_h + wo + (size_t)n0 * DOUT};
    run_gemm_s(srcs, DOUT, DOUT, sb, tid, f, acc);

    const float g2 = sig_f(graw2[p]);
    const float* acc2 = g_acc2 + ao;
    const int wm = wid & 1, wn = wid >> 1;
    const int g = lane >> 2, t4 = lane & 3;
#pragma unroll
    for (int mi = 0; mi < 4; mi++)
#pragma unroll
        for (int ni = 0; ni < 4; ni++) {
            float* c1 = acc[mi * 4 + ni];
            int r0 = m0 + wm * 64 + mi * 16 + g;
            int col = n0 + wn * 32 + ni * 8 + t4 * 2;
            float2 b2 = *reinterpret_cast<const float2*>(&bias2[p * DOUT + col]);
            float2 ob = *reinterpret_cast<const float2*>(&obias[p * DOUT + col]);
            float2 a2a = *reinterpret_cast<const float2*>(&acc2[(size_t)r0 * DOUT + col]);
            float2 a2b = *reinterpret_cast<const float2*>(&acc2[(size_t)(r0 + 8) * DOUT + col]);
            float o0 = sp_f(sp_f((c1[0] + b2.x) * g2) + a2a.x) + ob.x;
            float o1 = sp_f(sp_f((c1[1] + b2.y) * g2) + a2a.y) + ob.y;
            *reinterpret_cast<float2*>(&out[(size_t)r0 * (PNUM * DOUT) + p * DOUT + col]) =
                make_float2(o0, o1);
            float o2 = sp_f(sp_f((c1[2] + b2.x) * g2) + a2b.x) + ob.x;
            float o3 = sp_f(sp_f((c1[3] + b2.y) * g2) + a2b.y) + ob.y;
            *reinterpret_cast<float2*>(&out[(size_t)(r0 + 8) * (PNUM * DOUT) + p * DOUT + col]) =
                make_float2(o2, o3);
        }
}

// ---------------- launch ----------------
extern "C" void kernel_launch(void* const* d_in, const int* in_sizes, int n_in,
                              void* d_out, int out_size) {
    const float* x        = (const float*)d_in[0];
    const float* phi_raw  = (const float*)d_in[1];
    const float* phi_bias = (const float*)d_in[2];
    const float* rw2      = (const float*)d_in[3];
    const float* bias2    = (const float*)d_in[4];
    const float* graw2    = (const float*)d_in[5];
    const float* zw       = (const float*)d_in[6];
    const float* graw     = (const float*)d_in[7];
    const float* obias    = (const float*)d_in[8];
    float* out = (float*)d_out;

    cudaFuncSetAttribute(gemmA_z0,    cudaFuncAttributeMaxDynamicSharedMemorySize, SMEM_S);
    cudaFuncSetAttribute(stageB2_mma, cudaFuncAttributeMaxDynamicSharedMemorySize, SMEM_T);
    cudaFuncSetAttribute(stageB1_mma, cudaFuncAttributeMaxDynamicSharedMemorySize, SMEM_S);

    prep_w_kernel<<<8192, 256>>>(phi_raw, rw2);
    prep_zw_kernel<<<dim3(16, 16, 8), 256>>>(zw);
    phi_kernel<<<8192, 256>>>(x);
    stageB2_mma<<<dim3(4, 32, 8), 256, SMEM_T>>>();
    gemmA_z0<<<dim3(4, 32), 256, SMEM_S>>>(phi_bias, graw);
    stageB1_mma<<<dim3(4, 32, 8), 256, SMEM_S>>>(bias2, graw2, obias, out);
}

// round 8
// speedup vs baseline: 2.2477x; 1.5837x over previous
#include <cuda_runtime.h>
#include <cuda_fp16.h>
#include <cstdint>

#define N_TOK 4096
#define DIN   512
#define DOUT  512
#define PNUM  8
#define QDIM  4096

// Smem tile rows of 64B, XOR-swizzled: off = row*64 + ((g ^ ((row>>1)&3))<<4)
// stageB: 128x128 CTA tile, 2x4 warps (warp 64x32), BUF = A(8K)+B(8K)
// gemmA : 128x64  CTA tile, 4x2 warps (warp 32x32), BUF = A(8K)+B(4K)
#define NST      4
#define BUF_SB   16384
#define SMEM_SB  (NST * BUF_SB)   // 65536
#define BUF_GA   12288
#define SMEM_GA  (NST * BUF_GA)   // 49152

// ---------------- scratch (static device globals) ----------------
__device__ __align__(128) __half g_phi[N_TOK * QDIM];        // 32 MB
__device__ __align__(128) __half g_wphi[DOUT * QDIM];        // 4 MB
__device__ __align__(128) __half g_x[N_TOK * DIN];           // 4 MB
__device__ __align__(128) __half g_w2[PNUM * DOUT * DOUT];   // 4 MB
__device__ __align__(128) __half g_zwT[PNUM * DOUT * DIN];   // 8 MB
__device__ __align__(128) __half g_z0[PNUM * N_TOK * DOUT];  // 32 MB
__device__ __align__(128) float  g_acc2[PNUM * N_TOK * DOUT];

// ---------------- helpers ----------------
__device__ __forceinline__ float sp_f(float v) {
    return fmaxf(v, 0.0f) + log1pf(expf(-fabsf(v)));
}
__device__ __forceinline__ float sig_f(float v) { return 1.0f / (1.0f + expf(-v)); }

__device__ __forceinline__ uint32_t smem_u32(const void* p) {
    uint32_t a;
    asm("{ .reg .u64 t; cvta.to.shared.u64 t, %1; cvt.u32.u64 %0, t; }" : "=r"(a) : "l"(p));
    return a;
}
__device__ __forceinline__ void cp16(uint32_t saddr, const void* g) {
    asm volatile("cp.async.cg.shared.global [%0], [%1], 16;" :: "r"(saddr), "l"(g));
}
__device__ __forceinline__ void ldsm4(uint32_t* r, uint32_t addr) {
    asm volatile("ldmatrix.sync.aligned.m8n8.x4.shared.b16 {%0,%1,%2,%3}, [%4];"
                 : "=r"(r[0]), "=r"(r[1]), "=r"(r[2]), "=r"(r[3]) : "r"(addr));
}
__device__ __forceinline__ void mma16816(float* c, const uint32_t* a, const uint32_t* b) {
    asm volatile(
        "mma.sync.aligned.m16n8k16.row.col.f32.f16.f16.f32 "
        "{%0,%1,%2,%3}, {%4,%5,%6,%7}, {%8,%9}, {%0,%1,%2,%3};"
        : "+f"(c[0]), "+f"(c[1]), "+f"(c[2]), "+f"(c[3])
        : "r"(a[0]), "r"(a[1]), "r"(a[2]), "r"(a[3]), "r"(b[0]), "r"(b[1]));
}

// ---------------- elementwise kernels ----------------
__global__ void prep_w_kernel(const float* __restrict__ phi_raw,
                              const float* __restrict__ rw2) {
    int idx = blockIdx.x * 256 + threadIdx.x;
    if (idx >= DOUT * QDIM) return;  // 2097152
    float s1 = sp_f(phi_raw[idx]);
    g_wphi[idx] = __float2half_rn(s1 * s1);
    float s2 = sp_f(rw2[idx]);
    g_w2[idx] = __float2half_rn(s2 * s2);
}

// zwT[p][e][c] = zw[p][c][e] + zw[p][c+512][e], coalesced via smem tile
__global__ void prep_zw_kernel(const float* __restrict__ zw) {
    __shared__ float s[32][33];
    const int p = blockIdx.z;
    const int e0 = blockIdx.x * 32;
    const int c0 = blockIdx.y * 32;
    const int tx = threadIdx.x & 31, ty = threadIdx.x >> 5;  // 32 x 8
    const float* zp = zw + (size_t)p * (2 * DIN * DOUT);
#pragma unroll
    for (int r = 0; r < 4; r++) {
        int c = c0 + ty + r * 8;
        s[ty + r * 8][tx] = zp[(size_t)c * DOUT + e0 + tx] +
                            zp[(size_t)(c + DIN) * DOUT + e0 + tx];
    }
    __syncthreads();
#pragma unroll
    for (int r = 0; r < 4; r++) {
        int e = e0 + ty + r * 8;
        size_t dst = (size_t)p * (DIN * DOUT) + (size_t)e * DIN + c0 + tx;
        g_zwT[dst] = __float2half_rn(s[tx][ty + r * 8]);
    }
}

__global__ void phi_kernel(const float* __restrict__ x) {
    int idx = blockIdx.x * 256 + threadIdx.x;  // N_TOK*DIN
    if (idx >= N_TOK * DIN) return;
    float v = x[idx];
    g_x[idx] = __float2half_rn(v);
    const float step = 2.0f / 7.0f;
    __half h8[8];
#pragma unroll
    for (int k = 0; k < 8; k++)
        h8[k] = __float2half_rn(sp_f(v - 1.0f + step * (float)k));
    *reinterpret_cast<uint4*>(&g_phi[(size_t)idx * 8]) = *reinterpret_cast<uint4*>(h8);
}

// ---------------- GEMM machinery ----------------
// BROWS = rows in the B tile (64 or 128). A tile always 128 rows at dst+0,
// B tile at dst+8192.
template <int BROWS>
__device__ __forceinline__ void load_ab(uint32_t dst, const __half* __restrict__ A,
                                        const __half* __restrict__ B,
                                        int ldk, int k0, int tid) {
    const int g = tid & 3;
    const int rb = tid >> 2;  // 0..63
    const __half* a = A + k0 + g * 8;
#pragma unroll
    for (int j = 0; j < 2; j++) {
        int row = rb + j * 64;
        cp16(dst + row * 64 + ((g ^ ((row >> 1) & 3)) << 4), a + (size_t)row * ldk);
    }
    const __half* b = B + k0 + g * 8;
#pragma unroll
    for (int j = 0; j < BROWS / 64; j++) {
        int row = rb + j * 64;
        cp16(dst + 8192 + row * 64 + ((g ^ ((row >> 1) & 3)) << 4), b + (size_t)row * ldk);
    }
    asm volatile("cp.async.commit_group;" ::: "memory");
}

struct FragAddr {
    uint32_t a_row, a_g0, xa, b_row, b_g0, xb;
    __device__ FragAddr(int lane, int wm, int wn, int wm_rows) {
        a_row = wm * wm_rows + (lane & 15);
        a_g0 = lane >> 4;
        xa = ((lane & 15) >> 1) & 3;
        b_row = wn * 32 + (lane & 7) + ((lane >> 4) & 1) * 8;
        b_g0 = (lane >> 3) & 1;
        xb = ((lane & 7) >> 1) & 3;
    }
};

// stageB compute: 4 m-frags x 4 n-frags
__device__ __forceinline__ void compute_sb(uint32_t base, const FragAddr& f, float (*acc)[4]) {
#pragma unroll
    for (int ks = 0; ks < 2; ks++) {
        uint32_t ag = ((f.a_g0 + ks * 2) ^ f.xa) << 4;
        uint32_t bg = ((f.b_g0 + ks * 2) ^ f.xb) << 4;
        uint32_t ah[4][4], bh[2][4];
#pragma unroll
        for (int mi = 0; mi < 4; mi++)
            ldsm4(ah[mi], base + (f.a_row + mi * 16) * 64 + ag);
#pragma unroll
        for (int pr = 0; pr < 2; pr++)
            ldsm4(bh[pr], base + 8192 + (f.b_row + pr * 16) * 64 + bg);
#pragma unroll
        for (int mi = 0; mi < 4; mi++)
#pragma unroll
            for (int ni = 0; ni < 4; ni++)
                mma16816(acc[mi * 4 + ni], ah[mi], &bh[ni >> 1][(ni & 1) * 2]);
    }
}

// gemmA compute: 2 m-frags x 4 n-frags
__device__ __forceinline__ void compute_ga(uint32_t base, const FragAddr& f, float (*acc)[4]) {
#pragma unroll
    for (int ks = 0; ks < 2; ks++) {
        uint32_t ag = ((f.a_g0 + ks * 2) ^ f.xa) << 4;
        uint32_t bg = ((f.b_g0 + ks * 2) ^ f.xb) << 4;
        uint32_t ah[2][4], bh[2][4];
#pragma unroll
        for (int mi = 0; mi < 2; mi++)
            ldsm4(ah[mi], base + (f.a_row + mi * 16) * 64 + ag);
#pragma unroll
        for (int pr = 0; pr < 2; pr++)
            ldsm4(bh[pr], base + 8192 + (f.b_row + pr * 16) * 64 + bg);
#pragma unroll
        for (int mi = 0; mi < 2; mi++)
#pragma unroll
            for (int ni = 0; ni < 4; ni++)
                mma16816(acc[mi * 4 + ni], ah[mi], &bh[ni >> 1][(ni & 1) * 2]);
    }
}

#define PIPE_WAIT(i, nch)                                            \
    if ((i) + 2 < (nch)) { asm volatile("cp.async.wait_group 2;" ::: "memory"); } \
    else if ((i) + 1 < (nch)) { asm volatile("cp.async.wait_group 1;" ::: "memory"); } \
    else { asm volatile("cp.async.wait_group 0;" ::: "memory"); }

template <int BROWS, int BUF, typename ComputeFn>
__device__ __forceinline__ void run_gemm(const __half* __restrict__ A,
                                         const __half* __restrict__ B, int ldk, int K,
                                         uint32_t sb, int tid, const FragAddr& f,
                                         float (*acc)[4], ComputeFn compute) {
    const int nch = K >> 5;
    load_ab<BROWS>(sb, A, B, ldk, 0, tid);
    load_ab<BROWS>(sb + BUF, A, B, ldk, 32, tid);
    load_ab<BROWS>(sb + 2 * BUF, A, B, ldk, 64, tid);
    int buf = 0;
    for (int i = 0; i < nch; i++) {
        PIPE_WAIT(i, nch);
        __syncthreads();
        if (i + 3 < nch) {
            int nb = buf + 3; if (nb >= NST) nb -= NST;
            load_ab<BROWS>(sb + nb * BUF, A, B, ldk, (i + 3) << 5, tid);
        }
        compute(sb + buf * BUF, f, acc);
        if (++buf == NST) buf = 0;
    }
}

// ---------------- GEMM kernels ----------------
// GEMM A (fp16): phi @ wphi^T + bias -> fused z0 = sp(xproj*g1[p]) for all experts
__global__ __launch_bounds__(256, 2) void gemmA_z0(const float* __restrict__ phi_bias,
                                                   const float* __restrict__ graw) {
    extern __shared__ char smem[];
    uint32_t sb = smem_u32(smem);
    const int tid = threadIdx.x, lane = tid & 31, wid = tid >> 5;
    const int wm = wid & 3, wn = wid >> 2;         // 4 x 2 warps
    const FragAddr f(lane, wm, wn, 32);
    const int m0 = blockIdx.y * 128, n0 = blockIdx.x * 64;

    float acc[8][4];
#pragma unroll
    for (int i = 0; i < 8; i++)
#pragma unroll
        for (int j = 0; j < 4; j++) acc[i][j] = 0.0f;

    run_gemm<64, BUF_GA>(g_phi + (size_t)m0 * QDIM, g_wphi + (size_t)n0 * QDIM,
                         QDIM, QDIM, sb, tid, f, acc,
                         [](uint32_t b, const FragAddr& fa, float (*a)[4]) { compute_ga(b, fa, a); });

    float g1[PNUM];
#pragma unroll
    for (int p = 0; p < PNUM; p++) g1[p] = sig_f(graw[p]);

    const int g = lane >> 2, t4 = lane & 3;
#pragma unroll
    for (int mi = 0; mi < 2; mi++)
#pragma unroll
        for (int ni = 0; ni < 4; ni++) {
            float* c = acc[mi * 4 + ni];
            int r0 = m0 + wm * 32 + mi * 16 + g;
            int col = n0 + wn * 32 + ni * 8 + t4 * 2;
            float2 b = *reinterpret_cast<const float2*>(&phi_bias[col]);
            float xp[4] = {c[0] + b.x, c[1] + b.y, c[2] + b.x, c[3] + b.y};
#pragma unroll
            for (int p = 0; p < PNUM; p++) {
                __half z[4];
#pragma unroll
                for (int q = 0; q < 4; q++)
                    z[q] = __float2half_rn(sp_f(xp[q] * g1[p]));
                size_t base = (size_t)p * (N_TOK * DOUT);
                *reinterpret_cast<uint32_t*>(&g_z0[base + (size_t)r0 * DOUT + col]) =
                    *reinterpret_cast<uint32_t*>(&z[0]);
                *reinterpret_cast<uint32_t*>(&g_z0[base + (size_t)(r0 + 8) * DOUT + col]) =
                    *reinterpret_cast<uint32_t*>(&z[2]);
            }
        }
}

// residual GEMM (fp16): acc2 = x @ zwT^T
__global__ __launch_bounds__(256, 2) void stageB2_mma() {
    extern __shared__ char smem[];
    uint32_t sb = smem_u32(smem);
    const int tid = threadIdx.x, lane = tid & 31, wid = tid >> 5;
    const int wm = wid & 1, wn = wid >> 1;         // 2 x 4 warps
    const FragAddr f(lane, wm, wn, 64);
    const int p = blockIdx.z;
    const int m0 = blockIdx.y * 128, n0 = blockIdx.x * 128;

    float acc[16][4];
#pragma unroll
    for (int i = 0; i < 16; i++)
#pragma unroll
        for (int j = 0; j < 4; j++) acc[i][j] = 0.0f;

    run_gemm<128, BUF_SB>(g_x + (size_t)m0 * DIN,
                          g_zwT + (size_t)p * (DIN * DOUT) + (size_t)n0 * DIN,
                          DIN, DIN, sb, tid, f, acc,
                          [](uint32_t b, const FragAddr& fa, float (*a)[4]) { compute_sb(b, fa, a); });

    float* C = g_acc2 + (size_t)p * (N_TOK * DOUT);
    const int g = lane >> 2, t4 = lane & 3;
#pragma unroll
    for (int mi = 0; mi < 4; mi++)
#pragma unroll
        for (int ni = 0; ni < 4; ni++) {
            float* c = acc[mi * 4 + ni];
            int r0 = m0 + wm * 64 + mi * 16 + g;
            int col = n0 + wn * 32 + ni * 8 + t4 * 2;
            *reinterpret_cast<float2*>(&C[(size_t)r0 * DOUT + col]) = make_float2(c[0], c[1]);
            *reinterpret_cast<float2*>(&C[(size_t)(r0 + 8) * DOUT + col]) = make_float2(c[2], c[3]);
        }
}

// main GEMM (fp16): z0 @ w2^T + fused nonlinear epilogue (reads acc2) -> out
__global__ __launch_bounds__(256, 2) void stageB1_mma(const float* __restrict__ bias2,
                                                      const float* __restrict__ graw2,
                                                      const float* __restrict__ obias,
                                                      float* __restrict__ out) {
    extern __shared__ char smem[];
    uint32_t sb = smem_u32(smem);
    const int tid = threadIdx.x, lane = tid & 31, wid = tid >> 5;
    const int wm = wid & 1, wn = wid >> 1;
    const FragAddr f(lane, wm, wn, 64);
    const int p = blockIdx.z;
    const int m0 = blockIdx.y * 128, n0 = blockIdx.x * 128;

    float acc[16][4];
#pragma unroll
    for (int i = 0; i < 16; i++)
#pragma unroll
        for (int j = 0; j < 4; j++) acc[i][j] = 0.0f;

    const size_t ao = (size_t)p * (N_TOK * DOUT);
    run_gemm<128, BUF_SB>(g_z0 + ao + (size_t)m0 * DOUT,
                          g_w2 + (size_t)p * (DOUT * DOUT) + (size_t)n0 * DOUT,
                          DOUT, DOUT, sb, tid, f, acc,
                          [](uint32_t b, const FragAddr& fa, float (*a)[4]) { compute_sb(b, fa, a); });

    const float g2 = sig_f(graw2[p]);
    const float* acc2 = g_acc2 + ao;
    const int g = lane >> 2, t4 = lane & 3;
#pragma unroll
    for (int mi = 0; mi < 4; mi++)
#pragma unroll
        for (int ni = 0; ni < 4; ni++) {
            float* c1 = acc[mi * 4 + ni];
            int r0 = m0 + wm * 64 + mi * 16 + g;
            int col = n0 + wn * 32 + ni * 8 + t4 * 2;
            float2 b2 = *reinterpret_cast<const float2*>(&bias2[p * DOUT + col]);
            float2 ob = *reinterpret_cast<const float2*>(&obias[p * DOUT + col]);
            float2 a2a = *reinterpret_cast<const float2*>(&acc2[(size_t)r0 * DOUT + col]);
            float2 a2b = *reinterpret_cast<const float2*>(&acc2[(size_t)(r0 + 8) * DOUT + col]);
            float o0 = sp_f(sp_f((c1[0] + b2.x) * g2) + a2a.x) + ob.x;
            float o1 = sp_f(sp_f((c1[1] + b2.y) * g2) + a2a.y) + ob.y;
            *reinterpret_cast<float2*>(&out[(size_t)r0 * (PNUM * DOUT) + p * DOUT + col]) =
                make_float2(o0, o1);
            float o2 = sp_f(sp_f((c1[2] + b2.x) * g2) + a2b.x) + ob.x;
            float o3 = sp_f(sp_f((c1[3] + b2.y) * g2) + a2b.y) + ob.y;
            *reinterpret_cast<float2*>(&out[(size_t)(r0 + 8) * (PNUM * DOUT) + p * DOUT + col]) =
                make_float2(o2, o3);
        }
}

// ---------------- launch ----------------
extern "C" void kernel_launch(void* const* d_in, const int* in_sizes, int n_in,
                              void* d_out, int out_size) {
    const float* x        = (const float*)d_in[0];
    const float* phi_raw  = (const float*)d_in[1];
    const float* phi_bias = (const float*)d_in[2];
    const float* rw2      = (const float*)d_in[3];
    const float* bias2    = (const float*)d_in[4];
    const float* graw2    = (const float*)d_in[5];
    const float* zw       = (const float*)d_in[6];
    const float* graw     = (const float*)d_in[7];
    const float* obias    = (const float*)d_in[8];
    float* out = (float*)d_out;

    cudaFuncSetAttribute(gemmA_z0,    cudaFuncAttributeMaxDynamicSharedMemorySize, SMEM_GA);
    cudaFuncSetAttribute(stageB2_mma, cudaFuncAttributeMaxDynamicSharedMemorySize, SMEM_SB);
    cudaFuncSetAttribute(stageB1_mma, cudaFuncAttributeMaxDynamicSharedMemorySize, SMEM_SB);

    prep_w_kernel<<<8192, 256>>>(phi_raw, rw2);
    prep_zw_kernel<<<dim3(16, 16, 8), 256>>>(zw);
    phi_kernel<<<8192, 256>>>(x);
    stageB2_mma<<<dim3(4, 32, 8), 256, SMEM_SB>>>();
    gemmA_z0<<<dim3(8, 32), 256, SMEM_GA>>>(phi_bias, graw);
    stageB1_mma<<<dim3(4, 32, 8), 256, SMEM_SB>>>(bias2, graw2, obias, out);
}

// round 9
// speedup vs baseline: 3.0293x; 1.3477x over previous
#include <cuda_runtime.h>
#include <cuda_fp16.h>
#include <cstdint>

#define N_TOK 4096
#define DIN   512
#define DOUT  512
#define PNUM  8
#define QDIM  4096

// Smem tile rows of 64B, XOR-swizzled: off = row*64 + ((g ^ ((row>>1)&3))<<4)
// stageB: 128x128 CTA tile, 2x4 warps (warp 64x32), BUF = A(8K)+B(8K)
// gemmA : 128x64  CTA tile, 4x2 warps (warp 32x32), BUF = A(8K)+B(4K)
#define NST      4
#define BUF_SB   16384
#define SMEM_SB  (NST * BUF_SB)   // 65536
#define BUF_GA   12288

// ---------------- scratch (static device globals) ----------------
__device__ __align__(128) __half g_phi[N_TOK * QDIM];
__device__ __align__(128) __half g_wphi[DOUT * QDIM];
__device__ __align__(128) __half g_x[N_TOK * DIN];
__device__ __align__(128) __half g_w2[PNUM * DOUT * DOUT];
__device__ __align__(128) __half g_zwT[PNUM * DOUT * DIN];
__device__ __align__(128) __half g_z0[PNUM * N_TOK * DOUT];
__device__ __align__(128) float  g_acc2[PNUM * N_TOK * DOUT];

// ---------------- helpers ----------------
// fast softplus: MUFU-based. arg of log in (1,2] -> abs err ~1e-6
__device__ __forceinline__ float sp_f(float v) {
    return fmaxf(v, 0.0f) + __logf(1.0f + __expf(-fabsf(v)));
}
__device__ __forceinline__ float sig_f(float v) { return 1.0f / (1.0f + __expf(-v)); }

__device__ __forceinline__ uint32_t smem_u32(const void* p) {
    uint32_t a;
    asm("{ .reg .u64 t; cvta.to.shared.u64 t, %1; cvt.u32.u64 %0, t; }" : "=r"(a) : "l"(p));
    return a;
}
__device__ __forceinline__ void cp16(uint32_t saddr, const void* g) {
    asm volatile("cp.async.cg.shared.global [%0], [%1], 16;" :: "r"(saddr), "l"(g));
}
__device__ __forceinline__ void ldsm4(uint32_t* r, uint32_t addr) {
    asm volatile("ldmatrix.sync.aligned.m8n8.x4.shared.b16 {%0,%1,%2,%3}, [%4];"
                 : "=r"(r[0]), "=r"(r[1]), "=r"(r[2]), "=r"(r[3]) : "r"(addr));
}
__device__ __forceinline__ void mma16816(float* c, const uint32_t* a, const uint32_t* b) {
    asm volatile(
        "mma.sync.aligned.m16n8k16.row.col.f32.f16.f16.f32 "
        "{%0,%1,%2,%3}, {%4,%5,%6,%7}, {%8,%9}, {%0,%1,%2,%3};"
        : "+f"(c[0]), "+f"(c[1]), "+f"(c[2]), "+f"(c[3])
        : "r"(a[0]), "r"(a[1]), "r"(a[2]), "r"(a[3]), "r"(b[0]), "r"(b[1]));
}

// ---------------- merged elementwise prep (one launch) ----------------
// blocks [0, 8192)      : prep_w   (wphi, w2)
// blocks [8192, 16384)  : phi      (g_x, g_phi)
// blocks [16384, 18432) : prep_zw  (zwT transpose+fold)
__global__ void prep_all(const float* __restrict__ phi_raw,
                         const float* __restrict__ rw2,
                         const float* __restrict__ x,
                         const float* __restrict__ zw) {
    const int b = blockIdx.x;
    if (b < 8192) {
        int idx = b * 256 + threadIdx.x;
        float s1 = sp_f(phi_raw[idx]);
        g_wphi[idx] = __float2half_rn(s1 * s1);
        float s2 = sp_f(rw2[idx]);
        g_w2[idx] = __float2half_rn(s2 * s2);
    } else if (b < 16384) {
        int idx = (b - 8192) * 256 + threadIdx.x;
        float v = x[idx];
        g_x[idx] = __float2half_rn(v);
        const float step = 2.0f / 7.0f;
        __half h8[8];
#pragma unroll
        for (int k = 0; k < 8; k++)
            h8[k] = __float2half_rn(sp_f(v - 1.0f + step * (float)k));
        *reinterpret_cast<uint4*>(&g_phi[(size_t)idx * 8]) = *reinterpret_cast<uint4*>(h8);
    } else {
        __shared__ float s[32][33];
        const int bi = b - 16384;
        const int e0 = (bi & 15) * 32;
        const int c0 = ((bi >> 4) & 15) * 32;
        const int p = bi >> 8;
        const int tx = threadIdx.x & 31, ty = threadIdx.x >> 5;  // 32 x 8
        const float* zp = zw + (size_t)p * (2 * DIN * DOUT);
#pragma unroll
        for (int r = 0; r < 4; r++) {
            int c = c0 + ty + r * 8;
            s[ty + r * 8][tx] = zp[(size_t)c * DOUT + e0 + tx] +
                                zp[(size_t)(c + DIN) * DOUT + e0 + tx];
        }
        __syncthreads();
#pragma unroll
        for (int r = 0; r < 4; r++) {
            int e = e0 + ty + r * 8;
            size_t dst = (size_t)p * (DIN * DOUT) + (size_t)e * DIN + c0 + tx;
            g_zwT[dst] = __float2half_rn(s[tx][ty + r * 8]);
        }
    }
}

// ---------------- GEMM machinery ----------------
template <int BROWS>
__device__ __forceinline__ void load_ab(uint32_t dst, const __half* __restrict__ A,
                                        const __half* __restrict__ B,
                                        int ldk, int k0, int tid) {
    const int g = tid & 3;
    const int rb = tid >> 2;  // 0..63
    const __half* a = A + k0 + g * 8;
#pragma unroll
    for (int j = 0; j < 2; j++) {
        int row = rb + j * 64;
        cp16(dst + row * 64 + ((g ^ ((row >> 1) & 3)) << 4), a + (size_t)row * ldk);
    }
    const __half* b = B + k0 + g * 8;
#pragma unroll
    for (int j = 0; j < BROWS / 64; j++) {
        int row = rb + j * 64;
        cp16(dst + 8192 + row * 64 + ((g ^ ((row >> 1) & 3)) << 4), b + (size_t)row * ldk);
    }
    asm volatile("cp.async.commit_group;" ::: "memory");
}

struct FragAddr {
    uint32_t a_row, a_g0, xa, b_row, b_g0, xb;
    __device__ FragAddr(int lane, int wm, int wn, int wm_rows) {
        a_row = wm * wm_rows + (lane & 15);
        a_g0 = lane >> 4;
        xa = ((lane & 15) >> 1) & 3;
        b_row = wn * 32 + (lane & 7) + ((lane >> 4) & 1) * 8;
        b_g0 = (lane >> 3) & 1;
        xb = ((lane & 7) >> 1) & 3;
    }
};

// stageB compute: 4 m-frags x 4 n-frags
__device__ __forceinline__ void compute_sb(uint32_t base, const FragAddr& f, float (*acc)[4]) {
#pragma unroll
    for (int ks = 0; ks < 2; ks++) {
        uint32_t ag = ((f.a_g0 + ks * 2) ^ f.xa) << 4;
        uint32_t bg = ((f.b_g0 + ks * 2) ^ f.xb) << 4;
        uint32_t ah[4][4], bh[2][4];
#pragma unroll
        for (int mi = 0; mi < 4; mi++)
            ldsm4(ah[mi], base + (f.a_row + mi * 16) * 64 + ag);
#pragma unroll
        for (int pr = 0; pr < 2; pr++)
            ldsm4(bh[pr], base + 8192 + (f.b_row + pr * 16) * 64 + bg);
#pragma unroll
        for (int mi = 0; mi < 4; mi++)
#pragma unroll
            for (int ni = 0; ni < 4; ni++)
                mma16816(acc[mi * 4 + ni], ah[mi], &bh[ni >> 1][(ni & 1) * 2]);
    }
}

// gemmA compute: 2 m-frags x 4 n-frags
__device__ __forceinline__ void compute_ga(uint32_t base, const FragAddr& f, float (*acc)[4]) {
#pragma unroll
    for (int ks = 0; ks < 2; ks++) {
        uint32_t ag = ((f.a_g0 + ks * 2) ^ f.xa) << 4;
        uint32_t bg = ((f.b_g0 + ks * 2) ^ f.xb) << 4;
        uint32_t ah[2][4], bh[2][4];
#pragma unroll
        for (int mi = 0; mi < 2; mi++)
            ldsm4(ah[mi], base + (f.a_row + mi * 16) * 64 + ag);
#pragma unroll
        for (int pr = 0; pr < 2; pr++)
            ldsm4(bh[pr], base + 8192 + (f.b_row + pr * 16) * 64 + bg);
#pragma unroll
        for (int mi = 0; mi < 2; mi++)
#pragma unroll
            for (int ni = 0; ni < 4; ni++)
                mma16816(acc[mi * 4 + ni], ah[mi], &bh[ni >> 1][(ni & 1) * 2]);
    }
}

#define PIPE_WAIT(i, nch)                                                         \
    if ((i) + 2 < (nch)) { asm volatile("cp.async.wait_group 2;" ::: "memory"); } \
    else if ((i) + 1 < (nch)) { asm volatile("cp.async.wait_group 1;" ::: "memory"); } \
    else { asm volatile("cp.async.wait_group 0;" ::: "memory"); }

template <int BROWS, int BUF, typename ComputeFn>
__device__ __forceinline__ void run_gemm(const __half* __restrict__ A,
                                         const __half* __restrict__ B, int ldk, int K,
                                         uint32_t sb, int tid, const FragAddr& f,
                                         float (*acc)[4], ComputeFn compute) {
    const int nch = K >> 5;
    load_ab<BROWS>(sb, A, B, ldk, 0, tid);
    load_ab<BROWS>(sb + BUF, A, B, ldk, 32, tid);
    load_ab<BROWS>(sb + 2 * BUF, A, B, ldk, 64, tid);
    int buf = 0;
    for (int i = 0; i < nch; i++) {
        PIPE_WAIT(i, nch);
        __syncthreads();
        if (i + 3 < nch) {
            int nb = buf + 3; if (nb >= NST) nb -= NST;
            load_ab<BROWS>(sb + nb * BUF, A, B, ldk, (i + 3) << 5, tid);
        }
        compute(sb + buf * BUF, f, acc);
        if (++buf == NST) buf = 0;
    }
}

// ---------------- combined gemmA_z0 + stageB2 (one launch; independent work) ----------------
// grid (4, 32, 10): z<8 -> stageB2 expert z ; z in {8,9} -> gemmA n-tile (z-8)*4+x
__global__ __launch_bounds__(256, 2) void gemmAB2(const float* __restrict__ phi_bias,
                                                  const float* __restrict__ graw) {
    extern __shared__ char smem[];
    uint32_t sb = smem_u32(smem);
    const int tid = threadIdx.x, lane = tid & 31, wid = tid >> 5;
    const int z = blockIdx.z;

    if (z < PNUM) {
        // ---- stageB2: acc2 = x @ zwT^T for expert z ----
        const int wm = wid & 1, wn = wid >> 1;
        const FragAddr f(lane, wm, wn, 64);
        const int m0 = blockIdx.y * 128, n0 = blockIdx.x * 128;

        float acc[16][4];
#pragma unroll
        for (int i = 0; i < 16; i++)
#pragma unroll
            for (int j = 0; j < 4; j++) acc[i][j] = 0.0f;

        run_gemm<128, BUF_SB>(g_x + (size_t)m0 * DIN,
                              g_zwT + (size_t)z * (DIN * DOUT) + (size_t)n0 * DIN,
                              DIN, DIN, sb, tid, f, acc,
                              [](uint32_t b, const FragAddr& fa, float (*a)[4]) { compute_sb(b, fa, a); });

        float* C = g_acc2 + (size_t)z * (N_TOK * DOUT);
        const int g = lane >> 2, t4 = lane & 3;
#pragma unroll
        for (int mi = 0; mi < 4; mi++)
#pragma unroll
            for (int ni = 0; ni < 4; ni++) {
                float* c = acc[mi * 4 + ni];
                int r0 = m0 + wm * 64 + mi * 16 + g;
                int col = n0 + wn * 32 + ni * 8 + t4 * 2;
                *reinterpret_cast<float2*>(&C[(size_t)r0 * DOUT + col]) = make_float2(c[0], c[1]);
                *reinterpret_cast<float2*>(&C[(size_t)(r0 + 8) * DOUT + col]) = make_float2(c[2], c[3]);
            }
    } else {
        // ---- gemmA: phi @ wphi^T + bias -> z0 for all experts ----
        const int wm = wid & 3, wn = wid >> 2;     // 4 x 2 warps
        const FragAddr f(lane, wm, wn, 32);
        const int m0 = blockIdx.y * 128;
        const int n0 = ((z - PNUM) * 4 + blockIdx.x) * 64;

        float acc[8][4];
#pragma unroll
        for (int i = 0; i < 8; i++)
#pragma unroll
            for (int j = 0; j < 4; j++) acc[i][j] = 0.0f;

        run_gemm<64, BUF_GA>(g_phi + (size_t)m0 * QDIM, g_wphi + (size_t)n0 * QDIM,
                             QDIM, QDIM, sb, tid, f, acc,
                             [](uint32_t b, const FragAddr& fa, float (*a)[4]) { compute_ga(b, fa, a); });

        float g1[PNUM];
#pragma unroll
        for (int p = 0; p < PNUM; p++) g1[p] = sig_f(graw[p]);

        const int g = lane >> 2, t4 = lane & 3;
#pragma unroll
        for (int mi = 0; mi < 2; mi++)
#pragma unroll
            for (int ni = 0; ni < 4; ni++) {
                float* c = acc[mi * 4 + ni];
                int r0 = m0 + wm * 32 + mi * 16 + g;
                int col = n0 + wn * 32 + ni * 8 + t4 * 2;
                float2 b = *reinterpret_cast<const float2*>(&phi_bias[col]);
                float xp[4] = {c[0] + b.x, c[1] + b.y, c[2] + b.x, c[3] + b.y};
#pragma unroll
                for (int p = 0; p < PNUM; p++) {
                    __half zq[4];
#pragma unroll
                    for (int q = 0; q < 4; q++)
                        zq[q] = __float2half_rn(sp_f(xp[q] * g1[p]));
                    size_t base = (size_t)p * (N_TOK * DOUT);
                    *reinterpret_cast<uint32_t*>(&g_z0[base + (size_t)r0 * DOUT + col]) =
                        *reinterpret_cast<uint32_t*>(&zq[0]);
                    *reinterpret_cast<uint32_t*>(&g_z0[base + (size_t)(r0 + 8) * DOUT + col]) =
                        *reinterpret_cast<uint32_t*>(&zq[2]);
                }
            }
    }
}

// ---------------- stageB1: z0 @ w2^T + fused nonlinear epilogue -> out ----------------
__global__ __launch_bounds__(256, 2) void stageB1_mma(const float* __restrict__ bias2,
                                                      const float* __restrict__ graw2,
                                                      const float* __restrict__ obias,
                                                      float* __restrict__ out) {
    extern __shared__ char smem[];
    uint32_t sb = smem_u32(smem);
    const int tid = threadIdx.x, lane = tid & 31, wid = tid >> 5;
    const int wm = wid & 1, wn = wid >> 1;
    const FragAddr f(lane, wm, wn, 64);
    const int p = blockIdx.z;
    const int m0 = blockIdx.y * 128, n0 = blockIdx.x * 128;

    float acc[16][4];
#pragma unroll
    for (int i = 0; i < 16; i++)
#pragma unroll
        for (int j = 0; j < 4; j++) acc[i][j] = 0.0f;

    const size_t ao = (size_t)p * (N_TOK * DOUT);
    run_gemm<128, BUF_SB>(g_z0 + ao + (size_t)m0 * DOUT,
                          g_w2 + (size_t)p * (DOUT * DOUT) + (size_t)n0 * DOUT,
                          DOUT, DOUT, sb, tid, f, acc,
                          [](uint32_t b, const FragAddr& fa, float (*a)[4]) { compute_sb(b, fa, a); });

    const float g2 = sig_f(graw2[p]);
    const float* acc2 = g_acc2 + ao;
    const int g = lane >> 2, t4 = lane & 3;
#pragma unroll
    for (int mi = 0; mi < 4; mi++)
#pragma unroll
        for (int ni = 0; ni < 4; ni++) {
            float* c1 = acc[mi * 4 + ni];
            int r0 = m0 + wm * 64 + mi * 16 + g;
            int col = n0 + wn * 32 + ni * 8 + t4 * 2;
            float2 b2 = *reinterpret_cast<const float2*>(&bias2[p * DOUT + col]);
            float2 ob = *reinterpret_cast<const float2*>(&obias[p * DOUT + col]);
            float2 a2a = *reinterpret_cast<const float2*>(&acc2[(size_t)r0 * DOUT + col]);
            float2 a2b = *reinterpret_cast<const float2*>(&acc2[(size_t)(r0 + 8) * DOUT + col]);
            float o0 = sp_f(sp_f((c1[0] + b2.x) * g2) + a2a.x) + ob.x;
            float o1 = sp_f(sp_f((c1[1] + b2.y) * g2) + a2a.y) + ob.y;
            *reinterpret_cast<float2*>(&out[(size_t)r0 * (PNUM * DOUT) + p * DOUT + col]) =
                make_float2(o0, o1);
            float o2 = sp_f(sp_f((c1[2] + b2.x) * g2) + a2b.x) + ob.x;
            float o3 = sp_f(sp_f((c1[3] + b2.y) * g2) + a2b.y) + ob.y;
            *reinterpret_cast<float2*>(&out[(size_t)(r0 + 8) * (PNUM * DOUT) + p * DOUT + col]) =
                make_float2(o2, o3);
        }
}

// ---------------- launch ----------------
extern "C" void kernel_launch(void* const* d_in, const int* in_sizes, int n_in,
                              void* d_out, int out_size) {
    const float* x        = (const float*)d_in[0];
    const float* phi_raw  = (const float*)d_in[1];
    const float* phi_bias = (const float*)d_in[2];
    const float* rw2      = (const float*)d_in[3];
    const float* bias2    = (const float*)d_in[4];
    const float* graw2    = (const float*)d_in[5];
    const float* zw       = (const float*)d_in[6];
    const float* graw     = (const float*)d_in[7];
    const float* obias    = (const float*)d_in[8];
    float* out = (float*)d_out;

    cudaFuncSetAttribute(gemmAB2,     cudaFuncAttributeMaxDynamicSharedMemorySize, SMEM_SB);
    cudaFuncSetAttribute(stageB1_mma, cudaFuncAttributeMaxDynamicSharedMemorySize, SMEM_SB);

    prep_all<<<18432, 256>>>(phi_raw, rw2, x, zw);
    gemmAB2<<<dim3(4, 32, 10), 256, SMEM_SB>>>(phi_bias, graw);
    stageB1_mma<<<dim3(4, 32, 8), 256, SMEM_SB>>>(bias2, graw2, obias, out);
}